// round 13
// baseline (speedup 1.0000x reference)
#include <cuda_runtime.h>
#include <cuda_fp16.h>

// Problem constants
#define NN    50000
#define EE    800000
#define ROWH  128     // fp16 table stride in halves = 256 B = 2 x 128B lines.
                      // o-major permuted: half idx = slot*8 + d; even o -> slot o/2, odd o -> slot 8+o/2.
#define MT    3125    // m-tiles of 16 nodes (50000 = 3125*16 exactly)
#define WSTRIDE 168   // Wt smem stride in floats: bank = t4*8+g -> conflict-free B-frag loads
#define SSTRIDE 136   // staging row stride in halves (272B, 16B-aligned)

// ---------------- scratch (static device memory; no runtime allocation) ----------------
__device__ __half g_TextH[(size_t)NN * ROWH];   // 12.8 MB
__device__ float  g_xb[NN * 16];
__device__ float  g_rootx[NN * 16];
__device__ float  g_agg0[NN * 16];
__device__ float  g_agg1[NN * 16];
__device__ float  g_cnt[NN];
__device__ int    g_is64;   // 1 if edge_index is int64, 0 if int32

// ---------------- helpers ----------------
__device__ __forceinline__ unsigned tf32_of(float f) {
    unsigned r;
    asm("cvt.rna.tf32.f32 %0, %1;" : "=r"(r) : "f"(f));
    return r;
}

__device__ __forceinline__ void mma_tf32(float& c0, float& c1, float& c2, float& c3,
                                         unsigned a0, unsigned a1, unsigned a2, unsigned a3,
                                         unsigned b0, unsigned b1) {
    asm("mma.sync.aligned.m16n8k8.row.col.f32.tf32.tf32.f32 "
        "{%0,%1,%2,%3},{%4,%5,%6,%7},{%8,%9},{%0,%1,%2,%3};"
        : "+f"(c0), "+f"(c1), "+f"(c2), "+f"(c3)
        : "r"(a0), "r"(a1), "r"(a2), "r"(a3), "r"(b0), "r"(b1));
}

// vectorized no-return atomic add (sm_90+, PTX ISA 8.1)
__device__ __forceinline__ void red2(float* p, float a, float b) {
    asm volatile("red.global.add.v2.f32 [%0], {%1, %2};"
                 :: "l"(p), "f"(a), "f"(b) : "memory");
}

// ---------------- kernels ----------------

// Tensor-core node prep via mma.sync.m16n8k8.tf32; one warp per 16-node tile.
// mode 0: input = x (global); also zeroes agg0/cnt, block0/warp0 probes dtype.
// mode 1: input = relu(agg0/max(cnt,1) + rootx) computed inline (fused relu_h);
//         also zeroes agg1.
// n-tiles 0..15 -> T (fp16 permuted, staged->coalesced), 16..17 -> xb, 18..19 -> rootx+bias.
__global__ void __launch_bounds__(256)
node_prep_kernel(const float* __restrict__ xin,
                 const float* __restrict__ nw,
                 const float* __restrict__ nb,
                 const float* __restrict__ rt,
                 const float* __restrict__ bs,
                 const void* __restrict__ ei,
                 int mode) {
    __shared__ unsigned Wt[16 * WSTRIDE];           // tf32 weights, [k][j]
    __shared__ float    Bs[16];                     // bias
    __shared__ __half   stage[8][16 * SSTRIDE];     // per-warp T staging

    if (mode == 0) {
        if (blockIdx.x == 0 && threadIdx.x < 32) {
            const unsigned long long* p = (const unsigned long long*)ei;
            int t = threadIdx.x;
            bool bad = (p[t] >= (unsigned long long)NN) ||
                       (p[t + 32] >= (unsigned long long)NN);
            unsigned m = __ballot_sync(0xffffffffu, bad);
            if (t == 0) g_is64 = (m == 0) ? 1 : 0;
        }
        int idx = blockIdx.x * blockDim.x + threadIdx.x;
        int stride = gridDim.x * blockDim.x;
        float4 z4 = make_float4(0.f, 0.f, 0.f, 0.f);
        for (int i = idx; i < NN * 4; i += stride)
            ((float4*)g_agg0)[i] = z4;
        for (int i = idx; i < NN; i += stride)
            g_cnt[i] = 0.f;
    } else {
        int idx = blockIdx.x * blockDim.x + threadIdx.x;
        int stride = gridDim.x * blockDim.x;
        float4 z4 = make_float4(0.f, 0.f, 0.f, 0.f);
        for (int i = idx; i < NN * 4; i += stride)
            ((float4*)g_agg1)[i] = z4;
    }

    // Stage weights as tf32: W[k=i][j], j<128: nn_w (d=j>>4,o=j&15); 128..143: nn_b; 144..159: root.
    for (int t = threadIdx.x; t < 16 * 160; t += blockDim.x) {
        int i = t / 160, j = t % 160;
        float w;
        if (j < 128) {
            int d = j >> 4, o = j & 15;
            w = nw[d * 256 + i * 16 + o];
        } else if (j < 144) {
            w = nb[i * 16 + (j - 128)];
        } else {
            w = rt[i * 16 + (j - 144)];
        }
        Wt[i * WSTRIDE + j] = tf32_of(w);
    }
    if (threadIdx.x < 16) Bs[threadIdx.x] = bs[threadIdx.x];
    __syncthreads();

    int wid = threadIdx.x >> 5;
    int lane = threadIdx.x & 31;
    int g = lane >> 2;          // group id 0..7
    int t4 = lane & 3;          // thread-in-group

    int m = blockIdx.x * 8 + wid;
    if (m >= MT) return;
    int base = m * 16;

    // A fragments (rows base+g, base+g+8; k = kh*8 + t4, +4)
    unsigned A[2][4];
    if (mode == 0) {
        const float* x0 = xin + (size_t)(base + g) * 16;
        const float* x1 = xin + (size_t)(base + g + 8) * 16;
#pragma unroll
        for (int kh = 0; kh < 2; kh++) {
            A[kh][0] = tf32_of(x0[kh * 8 + t4]);
            A[kh][1] = tf32_of(x1[kh * 8 + t4]);
            A[kh][2] = tf32_of(x0[kh * 8 + t4 + 4]);
            A[kh][3] = tf32_of(x1[kh * 8 + t4 + 4]);
        }
    } else {
        int r0 = base + g, r1 = base + g + 8;
        float inv0 = 1.f / fmaxf(g_cnt[r0], 1.f);
        float inv1 = 1.f / fmaxf(g_cnt[r1], 1.f);
        const float* a0p = g_agg0 + (size_t)r0 * 16;
        const float* a1p = g_agg0 + (size_t)r1 * 16;
        const float* x0p = g_rootx + (size_t)r0 * 16;
        const float* x1p = g_rootx + (size_t)r1 * 16;
#pragma unroll
        for (int kh = 0; kh < 2; kh++) {
            int k = kh * 8 + t4;
            A[kh][0] = tf32_of(fmaxf(fmaf(a0p[k], inv0, x0p[k]), 0.f));
            A[kh][1] = tf32_of(fmaxf(fmaf(a1p[k], inv1, x1p[k]), 0.f));
            A[kh][2] = tf32_of(fmaxf(fmaf(a0p[k + 4], inv0, x0p[k + 4]), 0.f));
            A[kh][3] = tf32_of(fmaxf(fmaf(a1p[k + 4], inv1, x1p[k + 4]), 0.f));
        }
    }

    __half* st = stage[wid];

#pragma unroll
    for (int nbt = 0; nbt < 20; nbt++) {
        float c0 = 0.f, c1 = 0.f, c2 = 0.f, c3 = 0.f;
#pragma unroll
        for (int kh = 0; kh < 2; kh++) {
            unsigned b0 = Wt[(kh * 8 + t4) * WSTRIDE + nbt * 8 + g];
            unsigned b1 = Wt[(kh * 8 + t4 + 4) * WSTRIDE + nbt * 8 + g];
            mma_tf32(c0, c1, c2, c3, A[kh][0], A[kh][1], A[kh][2], A[kh][3], b0, b1);
        }
        // C layout: c0=(row g, col 2*t4), c1=(g, 2*t4+1), c2=(g+8, 2*t4), c3=(g+8, 2*t4+1)
        if (nbt < 16) {
            int d = nbt >> 1;
            int o0 = (nbt & 1) * 8 + 2 * t4;
            int idx0 = (o0 >> 1) * 8 + d;     // even col slot; odd col = +64
            st[g * SSTRIDE + idx0]            = __float2half_rn(c0);
            st[g * SSTRIDE + idx0 + 64]       = __float2half_rn(c1);
            st[(g + 8) * SSTRIDE + idx0]      = __float2half_rn(c2);
            st[(g + 8) * SSTRIDE + idx0 + 64] = __float2half_rn(c3);
        } else if (nbt < 18) {
            int o0 = (nbt - 16) * 8 + 2 * t4;
            *(float2*)&g_xb[(size_t)(base + g) * 16 + o0]     = make_float2(c0, c1);
            *(float2*)&g_xb[(size_t)(base + g + 8) * 16 + o0] = make_float2(c2, c3);
        } else {
            int o0 = (nbt - 18) * 8 + 2 * t4;
            float b0v = Bs[o0], b1v = Bs[o0 + 1];
            *(float2*)&g_rootx[(size_t)(base + g) * 16 + o0]     = make_float2(c0 + b0v, c1 + b1v);
            *(float2*)&g_rootx[(size_t)(base + g + 8) * 16 + o0] = make_float2(c2 + b0v, c3 + b1v);
        }
    }
    __syncwarp();

    // Coalesced copy: staging rows (SSTRIDE halves) -> g_TextH rows (128 halves).
    for (int it = lane; it < 256; it += 32) {
        int r = it >> 4;
        int q = it & 15;
        float4 v = *(const float4*)(st + r * SSTRIDE + q * 8);
        *(float4*)((char*)(g_TextH + (size_t)(base + r) * ROWH) + q * 16) = v;
    }
}

// 8 cooperative lanes per edge, 2 edges per thread (e and e+EE/2) for doubled
// memory-level parallelism. Shuffle-free fp16 o-major gather: lane l loads
// T[:, 2l] and T[:, 2l+1] (one full 128B line per instruction per edge),
// computes msg[2l], msg[2l+1] in fp32, adds fp32 xb, one red.v2 per edge.
__global__ void __launch_bounds__(256)
edge_kernel(const void* __restrict__ ei_raw,
            const float* __restrict__ ea,
            int layer, int do_cnt) {
    int gt = blockIdx.x * blockDim.x + threadIdx.x;   // EE*4 threads, exact grid
    int l = gt & 7;
    int e0 = gt >> 3;
    int e1 = e0 + EE / 2;

    int s0, d0, s1, d1;
    if (g_is64) {
        const long long* ei = (const long long*)ei_raw;
        s0 = (int)ei[e0];       d0 = (int)ei[EE + e0];
        s1 = (int)ei[e1];       d1 = (int)ei[EE + e1];
    } else {
        const int* ei = (const int*)ei_raw;
        s0 = ei[e0];            d0 = ei[EE + e0];
        s1 = ei[e1];            d1 = ei[EE + e1];
    }
    bool ok0 = ((unsigned)s0 < NN) && ((unsigned)d0 < NN);
    bool ok1 = ((unsigned)s1 < NN) && ((unsigned)d1 < NN);
    if (!ok0) s0 = 0;
    if (!ok1) s1 = 0;

    const float4* ep0 = (const float4*)(ea + (size_t)e0 * 8);
    const float4* ep1 = (const float4*)(ea + (size_t)e1 * 8);
    float4 a00 = ep0[0], a01 = ep0[1];
    float4 a10 = ep1[0], a11 = ep1[1];

    const char* row0 = (const char*)(g_TextH + (size_t)s0 * ROWH);
    const char* row1 = (const char*)(g_TextH + (size_t)s1 * ROWH);
    float4 rA0 = *(const float4*)(row0 + 16 * l);
    float4 rB0 = *(const float4*)(row0 + 128 + 16 * l);
    float4 rA1 = *(const float4*)(row1 + 16 * l);
    float4 rB1 = *(const float4*)(row1 + 128 + 16 * l);
    float2 xb0 = *(const float2*)(g_xb + (size_t)s0 * 16 + 2 * l);
    float2 xb1 = *(const float2*)(g_xb + (size_t)s1 * 16 + 2 * l);

#define DOT8(m, r, w0, w1)                                        \
    do {                                                          \
        float2 f0 = __half22float2(*(__half2*)&(r).x);            \
        float2 f1 = __half22float2(*(__half2*)&(r).y);            \
        float2 f2 = __half22float2(*(__half2*)&(r).z);            \
        float2 f3 = __half22float2(*(__half2*)&(r).w);            \
        m = f0.x * (w0).x;                                        \
        m = fmaf(f0.y, (w0).y, m);                                \
        m = fmaf(f1.x, (w0).z, m);                                \
        m = fmaf(f1.y, (w0).w, m);                                \
        m = fmaf(f2.x, (w1).x, m);                                \
        m = fmaf(f2.y, (w1).y, m);                                \
        m = fmaf(f3.x, (w1).z, m);                                \
        m = fmaf(f3.y, (w1).w, m);                                \
    } while (0)

    float mA0, mB0, mA1, mB1;
    DOT8(mA0, rA0, a00, a01);
    DOT8(mB0, rB0, a00, a01);
    DOT8(mA1, rA1, a10, a11);
    DOT8(mB1, rB1, a10, a11);
#undef DOT8

    mA0 += xb0.x; mB0 += xb0.y;
    mA1 += xb1.x; mB1 += xb1.y;

    float* agg = layer ? g_agg1 : g_agg0;
    if (ok0) {
        red2(agg + (size_t)d0 * 16 + 2 * l, mA0, mB0);
        if (do_cnt && l == 0) atomicAdd(&g_cnt[d0], 1.0f);
    }
    if (ok1) {
        red2(agg + (size_t)d1 * 16 + 2 * l, mA1, mB1);
        if (do_cnt && l == 0) atomicAdd(&g_cnt[d1], 1.0f);
    }
}

// out[n] = sum_o relu(agg1[n,o]/max(cnt,1) + rootx[n,o]) * head_w[o] + head_b
__global__ void head_kernel(const float* __restrict__ hw,
                            const float* __restrict__ hb,
                            float* __restrict__ out) {
    int n = blockIdx.x * blockDim.x + threadIdx.x;
    if (n >= NN) return;
    float inv = 1.f / fmaxf(g_cnt[n], 1.f);
    const float4* ag = (const float4*)(g_agg1 + (size_t)n * 16);
    const float4* rx = (const float4*)(g_rootx + (size_t)n * 16);
    float s = hb[0];
#pragma unroll
    for (int q = 0; q < 4; q++) {
        float4 a = ag[q], r = rx[q];
        const float4 w = ((const float4*)hw)[q];
        s = fmaf(fmaxf(fmaf(a.x, inv, r.x), 0.f), w.x, s);
        s = fmaf(fmaxf(fmaf(a.y, inv, r.y), 0.f), w.y, s);
        s = fmaf(fmaxf(fmaf(a.z, inv, r.z), 0.f), w.z, s);
        s = fmaf(fmaxf(fmaf(a.w, inv, r.w), 0.f), w.w, s);
    }
    out[n] = s;
}

// ---------------- launch ----------------
extern "C" void kernel_launch(void* const* d_in, const int* in_sizes, int n_in,
                              void* d_out, int out_size) {
    const float* x     = (const float*)d_in[0];
    const void*  ei    = d_in[1];
    const float* ea    = (const float*)d_in[2];
    const float* nn_w0 = (const float*)d_in[3];
    const float* nn_b0 = (const float*)d_in[4];
    const float* root0 = (const float*)d_in[5];
    const float* bias0 = (const float*)d_in[6];
    const float* nn_w1 = (const float*)d_in[7];
    const float* nn_b1 = (const float*)d_in[8];
    const float* root1 = (const float*)d_in[9];
    const float* bias1 = (const float*)d_in[10];
    const float* headw = (const float*)d_in[11];
    const float* headb = (const float*)d_in[12];
    float* out = (float*)d_out;

    const int TB = 256;
    const int EB = (EE * 4 + TB - 1) / TB;   // 8 lanes/edge, 2 edges/thread
    const int PB = (MT + 7) / 8;             // 1 warp per m-tile, 8 warps/block

    node_prep_kernel<<<PB, TB>>>(x, nn_w0, nn_b0, root0, bias0, ei, /*mode=*/0);
    edge_kernel<<<EB, TB>>>(ei, ea, /*layer=*/0, /*do_cnt=*/1);
    node_prep_kernel<<<PB, TB>>>(nullptr, nn_w1, nn_b1, root1, bias1, ei, /*mode=*/1);
    edge_kernel<<<EB, TB>>>(ei, ea, /*layer=*/1, /*do_cnt=*/0);
    head_kernel<<<(NN + TB - 1) / TB, TB>>>(headw, headb, out);
}

// round 14
// speedup vs baseline: 1.0240x; 1.0240x over previous
#include <cuda_runtime.h>
#include <cuda_fp16.h>

// Problem constants
#define NN    50000
#define EE    800000
#define ROWH  128     // fp16 table stride in halves = 256 B = 2 x 128B lines.
                      // o-major permuted: half idx = slot*8 + d; even o -> slot o/2, odd o -> slot 8+o/2.
#define MT    3125    // m-tiles of 16 nodes (50000 = 3125*16 exactly)
#define WSTRIDE 168   // Wt smem stride in floats: bank = t4*8+g -> conflict-free B-frag loads
#define SSTRIDE 136   // staging row stride in halves (272B, 16B-aligned)

// ---------------- scratch (static device memory; no runtime allocation) ----------------
__device__ __half g_TextH[(size_t)NN * ROWH];   // 12.8 MB
__device__ float  g_xb[NN * 16];
__device__ float  g_rootx[NN * 16];
__device__ float  g_agg0[NN * 16];
__device__ float  g_agg1[NN * 16];
__device__ float  g_cnt[NN];
__device__ int    g_is64;   // 1 if edge_index is int64, 0 if int32

// ---------------- helpers ----------------
__device__ __forceinline__ unsigned tf32_of(float f) {
    unsigned r;
    asm("cvt.rna.tf32.f32 %0, %1;" : "=r"(r) : "f"(f));
    return r;
}

__device__ __forceinline__ void mma_tf32(float& c0, float& c1, float& c2, float& c3,
                                         unsigned a0, unsigned a1, unsigned a2, unsigned a3,
                                         unsigned b0, unsigned b1) {
    asm("mma.sync.aligned.m16n8k8.row.col.f32.tf32.tf32.f32 "
        "{%0,%1,%2,%3},{%4,%5,%6,%7},{%8,%9},{%0,%1,%2,%3};"
        : "+f"(c0), "+f"(c1), "+f"(c2), "+f"(c3)
        : "r"(a0), "r"(a1), "r"(a2), "r"(a3), "r"(b0), "r"(b1));
}

// vectorized no-return atomic add (sm_90+, PTX ISA 8.1)
__device__ __forceinline__ void red2(float* p, float a, float b) {
    asm volatile("red.global.add.v2.f32 [%0], {%1, %2};"
                 :: "l"(p), "f"(a), "f"(b) : "memory");
}

// ---------------- kernels ----------------

// Tensor-core node prep via mma.sync.m16n8k8.tf32; one warp per 16-node tile.
// mode 0: input = x (global); also zeroes agg0/cnt, block0/warp0 probes dtype.
// mode 1: input = relu(agg0/max(cnt,1) + rootx) computed inline (fused relu_h);
//         also zeroes agg1.
// n-tiles 0..15 -> T (fp16 permuted, staged->coalesced), 16..17 -> xb, 18..19 -> rootx+bias.
__global__ void __launch_bounds__(256)
node_prep_kernel(const float* __restrict__ xin,
                 const float* __restrict__ nw,
                 const float* __restrict__ nb,
                 const float* __restrict__ rt,
                 const float* __restrict__ bs,
                 const void* __restrict__ ei,
                 int mode) {
    __shared__ unsigned Wt[16 * WSTRIDE];           // tf32 weights, [k][j]
    __shared__ float    Bs[16];                     // bias
    __shared__ __half   stage[8][16 * SSTRIDE];     // per-warp T staging

    if (mode == 0) {
        if (blockIdx.x == 0 && threadIdx.x < 32) {
            const unsigned long long* p = (const unsigned long long*)ei;
            int t = threadIdx.x;
            bool bad = (p[t] >= (unsigned long long)NN) ||
                       (p[t + 32] >= (unsigned long long)NN);
            unsigned m = __ballot_sync(0xffffffffu, bad);
            if (t == 0) g_is64 = (m == 0) ? 1 : 0;
        }
        int idx = blockIdx.x * blockDim.x + threadIdx.x;
        int stride = gridDim.x * blockDim.x;
        float4 z4 = make_float4(0.f, 0.f, 0.f, 0.f);
        for (int i = idx; i < NN * 4; i += stride)
            ((float4*)g_agg0)[i] = z4;
        for (int i = idx; i < NN; i += stride)
            g_cnt[i] = 0.f;
    } else {
        int idx = blockIdx.x * blockDim.x + threadIdx.x;
        int stride = gridDim.x * blockDim.x;
        float4 z4 = make_float4(0.f, 0.f, 0.f, 0.f);
        for (int i = idx; i < NN * 4; i += stride)
            ((float4*)g_agg1)[i] = z4;
    }

    // Stage weights as tf32: W[k=i][j], j<128: nn_w (d=j>>4,o=j&15); 128..143: nn_b; 144..159: root.
    for (int t = threadIdx.x; t < 16 * 160; t += blockDim.x) {
        int i = t / 160, j = t % 160;
        float w;
        if (j < 128) {
            int d = j >> 4, o = j & 15;
            w = nw[d * 256 + i * 16 + o];
        } else if (j < 144) {
            w = nb[i * 16 + (j - 128)];
        } else {
            w = rt[i * 16 + (j - 144)];
        }
        Wt[i * WSTRIDE + j] = tf32_of(w);
    }
    if (threadIdx.x < 16) Bs[threadIdx.x] = bs[threadIdx.x];
    __syncthreads();

    int wid = threadIdx.x >> 5;
    int lane = threadIdx.x & 31;
    int g = lane >> 2;          // group id 0..7
    int t4 = lane & 3;          // thread-in-group

    int m = blockIdx.x * 8 + wid;
    if (m >= MT) return;
    int base = m * 16;

    // A fragments (rows base+g, base+g+8; k = kh*8 + t4, +4)
    unsigned A[2][4];
    if (mode == 0) {
        const float* x0 = xin + (size_t)(base + g) * 16;
        const float* x1 = xin + (size_t)(base + g + 8) * 16;
#pragma unroll
        for (int kh = 0; kh < 2; kh++) {
            A[kh][0] = tf32_of(x0[kh * 8 + t4]);
            A[kh][1] = tf32_of(x1[kh * 8 + t4]);
            A[kh][2] = tf32_of(x0[kh * 8 + t4 + 4]);
            A[kh][3] = tf32_of(x1[kh * 8 + t4 + 4]);
        }
    } else {
        int r0 = base + g, r1 = base + g + 8;
        float inv0 = 1.f / fmaxf(g_cnt[r0], 1.f);
        float inv1 = 1.f / fmaxf(g_cnt[r1], 1.f);
        const float* a0p = g_agg0 + (size_t)r0 * 16;
        const float* a1p = g_agg0 + (size_t)r1 * 16;
        const float* x0p = g_rootx + (size_t)r0 * 16;
        const float* x1p = g_rootx + (size_t)r1 * 16;
#pragma unroll
        for (int kh = 0; kh < 2; kh++) {
            int k = kh * 8 + t4;
            A[kh][0] = tf32_of(fmaxf(fmaf(a0p[k], inv0, x0p[k]), 0.f));
            A[kh][1] = tf32_of(fmaxf(fmaf(a1p[k], inv1, x1p[k]), 0.f));
            A[kh][2] = tf32_of(fmaxf(fmaf(a0p[k + 4], inv0, x0p[k + 4]), 0.f));
            A[kh][3] = tf32_of(fmaxf(fmaf(a1p[k + 4], inv1, x1p[k + 4]), 0.f));
        }
    }

    __half* st = stage[wid];

#pragma unroll
    for (int nbt = 0; nbt < 20; nbt++) {
        float c0 = 0.f, c1 = 0.f, c2 = 0.f, c3 = 0.f;
#pragma unroll
        for (int kh = 0; kh < 2; kh++) {
            unsigned b0 = Wt[(kh * 8 + t4) * WSTRIDE + nbt * 8 + g];
            unsigned b1 = Wt[(kh * 8 + t4 + 4) * WSTRIDE + nbt * 8 + g];
            mma_tf32(c0, c1, c2, c3, A[kh][0], A[kh][1], A[kh][2], A[kh][3], b0, b1);
        }
        // C layout: c0=(row g, col 2*t4), c1=(g, 2*t4+1), c2=(g+8, 2*t4), c3=(g+8, 2*t4+1)
        if (nbt < 16) {
            int d = nbt >> 1;
            int o0 = (nbt & 1) * 8 + 2 * t4;
            int idx0 = (o0 >> 1) * 8 + d;     // even col slot; odd col = +64
            st[g * SSTRIDE + idx0]            = __float2half_rn(c0);
            st[g * SSTRIDE + idx0 + 64]       = __float2half_rn(c1);
            st[(g + 8) * SSTRIDE + idx0]      = __float2half_rn(c2);
            st[(g + 8) * SSTRIDE + idx0 + 64] = __float2half_rn(c3);
        } else if (nbt < 18) {
            int o0 = (nbt - 16) * 8 + 2 * t4;
            *(float2*)&g_xb[(size_t)(base + g) * 16 + o0]     = make_float2(c0, c1);
            *(float2*)&g_xb[(size_t)(base + g + 8) * 16 + o0] = make_float2(c2, c3);
        } else {
            int o0 = (nbt - 18) * 8 + 2 * t4;
            float b0v = Bs[o0], b1v = Bs[o0 + 1];
            *(float2*)&g_rootx[(size_t)(base + g) * 16 + o0]     = make_float2(c0 + b0v, c1 + b1v);
            *(float2*)&g_rootx[(size_t)(base + g + 8) * 16 + o0] = make_float2(c2 + b0v, c3 + b1v);
        }
    }
    __syncwarp();

    // Coalesced copy: staging rows (SSTRIDE halves) -> g_TextH rows (128 halves).
    for (int it = lane; it < 256; it += 32) {
        int r = it >> 4;
        int q = it & 15;
        float4 v = *(const float4*)(st + r * SSTRIDE + q * 8);
        *(float4*)((char*)(g_TextH + (size_t)(base + r) * ROWH) + q * 16) = v;
    }
}

// 8 cooperative lanes per edge (1 edge per thread-group — the measured-best
// R12 form). Shuffle-free fp16 o-major gather: lane l loads T[:, 2l] and
// T[:, 2l+1] (one full 128B line per instruction per edge), computes
// msg[2l], msg[2l+1] in fp32, adds fp32 xb, one red.v2 per lane.
__global__ void __launch_bounds__(256)
edge_kernel(const void* __restrict__ ei_raw,
            const float* __restrict__ ea,
            int layer, int do_cnt) {
    int gt = blockIdx.x * blockDim.x + threadIdx.x;
    int e = gt >> 3;               // grid exact: EE*8 == 25000*256
    int l = gt & 7;

    int src, dst;
    if (g_is64) {
        const long long* ei = (const long long*)ei_raw;
        src = (int)ei[e];
        dst = (int)ei[EE + e];
    } else {
        const int* ei = (const int*)ei_raw;
        src = ei[e];
        dst = ei[EE + e];
    }
    bool ok = ((unsigned)src < NN) && ((unsigned)dst < NN);
    if (!ok) src = 0;

    const float4* eap = (const float4*)(ea + (size_t)e * 8);
    float4 a0 = eap[0], a1 = eap[1];

    const char* row = (const char*)(g_TextH + (size_t)src * ROWH);
    float4 rA = *(const float4*)(row + 16 * l);        // T[:, 2l]
    float4 rB = *(const float4*)(row + 128 + 16 * l);  // T[:, 2l+1]

    float mA, mB;
    {
        float2 f0 = __half22float2(*(__half2*)&rA.x);  // d0,d1
        float2 f1 = __half22float2(*(__half2*)&rA.y);  // d2,d3
        float2 f2 = __half22float2(*(__half2*)&rA.z);  // d4,d5
        float2 f3 = __half22float2(*(__half2*)&rA.w);  // d6,d7
        mA = f0.x * a0.x;
        mA = fmaf(f0.y, a0.y, mA);
        mA = fmaf(f1.x, a0.z, mA);
        mA = fmaf(f1.y, a0.w, mA);
        mA = fmaf(f2.x, a1.x, mA);
        mA = fmaf(f2.y, a1.y, mA);
        mA = fmaf(f3.x, a1.z, mA);
        mA = fmaf(f3.y, a1.w, mA);
    }
    {
        float2 f0 = __half22float2(*(__half2*)&rB.x);
        float2 f1 = __half22float2(*(__half2*)&rB.y);
        float2 f2 = __half22float2(*(__half2*)&rB.z);
        float2 f3 = __half22float2(*(__half2*)&rB.w);
        mB = f0.x * a0.x;
        mB = fmaf(f0.y, a0.y, mB);
        mB = fmaf(f1.x, a0.z, mB);
        mB = fmaf(f1.y, a0.w, mB);
        mB = fmaf(f2.x, a1.x, mB);
        mB = fmaf(f2.y, a1.y, mB);
        mB = fmaf(f3.x, a1.z, mB);
        mB = fmaf(f3.y, a1.w, mB);
    }

    float2 xb2 = *(const float2*)(g_xb + (size_t)src * 16 + 2 * l);
    mA += xb2.x;
    mB += xb2.y;

    if (ok) {
        float* dstp = (layer ? g_agg1 : g_agg0) + (size_t)dst * 16 + 2 * l;
        red2(dstp, mA, mB);
        if (do_cnt && l == 0) atomicAdd(&g_cnt[dst], 1.0f);
    }
}

// out[n] = sum_o relu(agg1[n,o]/max(cnt,1) + rootx[n,o]) * head_w[o] + head_b
__global__ void head_kernel(const float* __restrict__ hw,
                            const float* __restrict__ hb,
                            float* __restrict__ out) {
    int n = blockIdx.x * blockDim.x + threadIdx.x;
    if (n >= NN) return;
    float inv = 1.f / fmaxf(g_cnt[n], 1.f);
    const float4* ag = (const float4*)(g_agg1 + (size_t)n * 16);
    const float4* rx = (const float4*)(g_rootx + (size_t)n * 16);
    float s = hb[0];
#pragma unroll
    for (int q = 0; q < 4; q++) {
        float4 a = ag[q], r = rx[q];
        const float4 w = ((const float4*)hw)[q];
        s = fmaf(fmaxf(fmaf(a.x, inv, r.x), 0.f), w.x, s);
        s = fmaf(fmaxf(fmaf(a.y, inv, r.y), 0.f), w.y, s);
        s = fmaf(fmaxf(fmaf(a.z, inv, r.z), 0.f), w.z, s);
        s = fmaf(fmaxf(fmaf(a.w, inv, r.w), 0.f), w.w, s);
    }
    out[n] = s;
}

// ---------------- launch ----------------
extern "C" void kernel_launch(void* const* d_in, const int* in_sizes, int n_in,
                              void* d_out, int out_size) {
    const float* x     = (const float*)d_in[0];
    const void*  ei    = d_in[1];
    const float* ea    = (const float*)d_in[2];
    const float* nn_w0 = (const float*)d_in[3];
    const float* nn_b0 = (const float*)d_in[4];
    const float* root0 = (const float*)d_in[5];
    const float* bias0 = (const float*)d_in[6];
    const float* nn_w1 = (const float*)d_in[7];
    const float* nn_b1 = (const float*)d_in[8];
    const float* root1 = (const float*)d_in[9];
    const float* bias1 = (const float*)d_in[10];
    const float* headw = (const float*)d_in[11];
    const float* headb = (const float*)d_in[12];
    float* out = (float*)d_out;

    const int TB = 256;
    const int EB = (EE * 8 + TB - 1) / TB;   // 8 lanes per edge, 1 edge per group
    const int PB = (MT + 7) / 8;             // 1 warp per m-tile, 8 warps/block

    node_prep_kernel<<<PB, TB>>>(x, nn_w0, nn_b0, root0, bias0, ei, /*mode=*/0);
    edge_kernel<<<EB, TB>>>(ei, ea, /*layer=*/0, /*do_cnt=*/1);
    node_prep_kernel<<<PB, TB>>>(nullptr, nn_w1, nn_b1, root1, bias1, ei, /*mode=*/1);
    edge_kernel<<<EB, TB>>>(ei, ea, /*layer=*/1, /*do_cnt=*/0);
    head_kernel<<<(NN + TB - 1) / TB, TB>>>(headw, headb, out);
}